// round 15
// baseline (speedup 1.0000x reference)
#include <cuda_runtime.h>
#include <math.h>
#include <stdint.h>

#define TREE_TOTAL 2047
#define NG 64
#define NN (NG * TREE_TOTAL)      // 131008
#define NE (2 * NN)               // 262016
#define HD 256
#define HALF 128
#define NL 4
#define BN_EPS 1e-5f
#define LN_EPS 1e-5f

// ---------------- scratch (no allocation allowed) ----------------
__device__ float  g_h  [(size_t)NN * HD];
__device__ float  g_agg[(size_t)NN * HD];
__device__ float  g_y1 [(size_t)NN * HD];
__device__ float  g_y2 [(size_t)NN * HD];
__device__ float  g_root[NG * HD];
__device__ double g_sum [HD];     // zero-init; k_makescale re-zeroes after use
__device__ double g_sqsum[HD];
__device__ float  g_scale[HD];
__device__ float  g_shift[HD];
// pre-split weights: 8 matrices (W1 x4, W2 x4), [mat][row][kpair] bf16x2 words
__device__ uint32_t g_Wh[8 * 256 * 128];
__device__ uint32_t g_Wl[8 * 256 * 128];

// split two floats (even k, odd k) into hi/lo bf16x2 packed words
__device__ __forceinline__ void split2(float e, float o, uint32_t& hi, uint32_t& lo) {
    uint32_t h;
    asm("cvt.rn.bf16x2.f32 %0, %1, %2;" : "=r"(h) : "f"(o), "f"(e));
    float ef = __uint_as_float(h << 16);
    float of = __uint_as_float(h & 0xffff0000u);
    float re = e - ef;
    float ro = o - of;
    uint32_t l;
    asm("cvt.rn.bf16x2.f32 %0, %1, %2;" : "=r"(l) : "f"(ro), "f"(re));
    hi = h; lo = l;
}

// ---------------- pre-split all weight matrices ----------------
__global__ void k_splitW(const float* __restrict__ W1, const float* __restrict__ W2) {
    int idx = blockIdx.x * blockDim.x + threadIdx.x;   // 8*256*128
    if (idx >= 8 * 256 * 128) return;
    int p = idx & 127;          // kpair
    int r = (idx >> 7) & 255;   // row (output-n)
    int m = idx >> 15;          // matrix 0..7
    const float* W = (m < 4) ? (W1 + (size_t)m * HD * HD)
                             : (W2 + (size_t)(m - 4) * HD * HD);
    float e = W[r * HD + 2 * p];
    float o = W[r * HD + 2 * p + 1];
    uint32_t h, l;
    split2(e, o, h, l);
    g_Wh[idx] = h;
    g_Wl[idx] = l;
}

// ---------------- embedding: h = concat(emb_node[x0], emb_label[x1]) ----------------
__global__ void k_embed(const int* __restrict__ x,
                        const float* __restrict__ en,
                        const float* __restrict__ el) {
    int idx = blockIdx.x * blockDim.x + threadIdx.x;
    if (idx >= NN * 64) return;
    int n = idx >> 6, q = idx & 63;
    float4 v;
    if (q < 32) {
        int e = x[2 * n];
        v = ((const float4*)(en + (size_t)e * HALF))[q];
    } else {
        int e = x[2 * n + 1];
        v = ((const float4*)(el + (size_t)e * HALF))[q - 32];
    }
    ((float4*)(g_h + (size_t)n * HD))[q] = v;
}

// ---------------- edge scatter: agg[dst] += h[src] * w (vector reduction) --------
__global__ void k_scatter(const int* __restrict__ src, const int* __restrict__ dst,
                          const float* __restrict__ w) {
    int idx = blockIdx.x * blockDim.x + threadIdx.x;
    if (idx >= NE * 64) return;
    int e = idx >> 6, q = idx & 63;
    int s = src[e], d = dst[e];
    float ww = w[e];
    float4 v = ((const float4*)(g_h + (size_t)s * HD))[q];
    float* a = g_agg + (size_t)d * HD + q * 4;
    asm volatile("red.global.add.v4.f32 [%0], {%1, %2, %3, %4};"
                 :: "l"(a), "f"(v.x * ww), "f"(v.y * ww),
                    "f"(v.z * ww), "f"(v.w * ww) : "memory");
}

// ---------------- last layer: per-graph sum of all node features ----------------
__global__ void k_rootsum() {
    int g = blockIdx.x;
    int c = blockIdx.y;
    int t = threadIdx.x;
    int r0 = c * 256;
    int r1 = r0 + 256; if (r1 > TREE_TOTAL) r1 = TREE_TOTAL;
    float s = 0.f;
    const float* base = g_h + ((size_t)g * TREE_TOTAL) * HD + t;
    for (int r = r0; r < r1; r++) s += base[(size_t)r * HD];
    atomicAdd(&g_root[g * HD + t], s);
}

// ---------------- BN -> per-column scale/shift; re-zero stats ----------------
__global__ void k_makescale(const float* __restrict__ gamma, const float* __restrict__ beta) {
    int t = threadIdx.x;
    double m = g_sum[t] / (double)NN;
    double v = g_sqsum[t] / (double)NN - m * m;
    if (v < 0.0) v = 0.0;
    double rs = 1.0 / sqrt(v + (double)BN_EPS);
    float sc = gamma[t] * (float)rs;
    g_scale[t] = sc;
    g_shift[t] = beta[t] - (float)m * sc;
    g_sum[t] = 0.0;
    g_sqsum[t] = 0.0;
}

// ============================================================================
// BF16x3 tensor-core GEMM, full-width tiles: C[128,256] per CTA, grid = 1024.
// 3-stage pipeline: A LDG prefetch distance 2 (stsA one full iteration after
// its LDG), B cp.async 2 tiles deep, triple-buffered split smem.
// Fragment loads via ldmatrix.x4. 512 threads, 16 warps (4m x 4n),
// warp tile 32x64, BK=16.
// MODE 0: a = A1 + A2
// MODE 1: a = relu(A1 * g_scale[k] + g_shift[k])
// MODE 2: a = A1 + (row % 2047 == 0 ? g_root[row/2047] : 0)
// ============================================================================
#define RSTRIDE 12                  // row stride in u32 words (A and B)
#define A_WORDS (128 * RSTRIDE)     // 1536 per matrix
#define B_WORDS (256 * RSTRIDE)     // 3072 per matrix
#define STAGE_WORDS (2 * A_WORDS + 2 * B_WORDS)   // 9216
#define NSTAGE 3
#define STATS_OFF (NSTAGE * STAGE_WORDS)          // 27648
#define SMEM_WORDS (STATS_OFF + 512)
#define SMEM_BYTES (SMEM_WORDS * 4)               // 112640

__device__ __forceinline__ void cp16(uint32_t saddr, const void* gptr) {
    asm volatile("cp.async.cg.shared.global [%0], [%1], 16;"
                 :: "r"(saddr), "l"(gptr) : "memory");
}
#define LDMX4(d0, d1, d2, d3, addr)                                           \
    asm volatile("ldmatrix.sync.aligned.m8n8.x4.shared.b16 {%0,%1,%2,%3}, [%4];" \
                 : "=r"(d0), "=r"(d1), "=r"(d2), "=r"(d3) : "r"(addr))

template <int MODE>
__global__ void __launch_bounds__(512, 1)
k_gemm_tc(const float* __restrict__ A1, const float* __restrict__ A2,
          const uint32_t* __restrict__ Wh, const uint32_t* __restrict__ Wl,
          const float* __restrict__ bias, float* __restrict__ C) {
    extern __shared__ uint32_t dyn[];
    float* s_sum = (float*)(dyn + STATS_OFF);
    float* s_ss  = (float*)(dyn + STATS_OFF + 256);
    const uint32_t smem_base = (uint32_t)__cvta_generic_to_shared(dyn);

    const int m0 = blockIdx.x * 128;
    const int tid = threadIdx.x;
    const int lane = tid & 31;
    const int warp = tid >> 5;
    const int wm = warp & 3;        // 32-row slab (4)
    const int wn = warp >> 2;       // 64-col slab (4)

    // A loader: 1 float4 per K-tile; 128 rows x 4 threads
    const int a_row = tid >> 2;     // 0..127
    const int a_kq  = tid & 3;      // float4 within 16-wide k
    // B loader: 16B hi + 16B lo per thread
    const int b_row = tid >> 1;     // 0..255
    const int b_c   = tid & 1;      // half-row chunk

    const int grow = m0 + a_row;
    const bool rok = grow < NN;
    const float* rootrow = nullptr;
    if (MODE == 2 && rok && (grow % TREE_TOTAL) == 0)
        rootrow = g_root + (grow / TREE_TOTAL) * HD;

    if (tid < 256) { s_sum[tid] = 0.f; s_ss[tid] = 0.f; }

    float acc[2][8][4];
#pragma unroll
    for (int i = 0; i < 2; i++)
#pragma unroll
        for (int j = 0; j < 8; j++)
#pragma unroll
            for (int q = 0; q < 4; q++) acc[i][j][q] = 0.f;

    float4 va[2];

    auto ldgA = [&](int kt, float4& v) {
        int kg = kt * 16 + a_kq * 4;
        if (rok) {
            v = *(const float4*)(A1 + (size_t)grow * HD + kg);
            if (MODE == 0) {
                float4 w4 = *(const float4*)(A2 + (size_t)grow * HD + kg);
                v.x += w4.x; v.y += w4.y; v.z += w4.z; v.w += w4.w;
            } else if (MODE == 1) {
                float4 sc = *(const float4*)(g_scale + kg);
                float4 sh = *(const float4*)(g_shift + kg);
                v.x = fmaxf(v.x * sc.x + sh.x, 0.f);
                v.y = fmaxf(v.y * sc.y + sh.y, 0.f);
                v.z = fmaxf(v.z * sc.z + sh.z, 0.f);
                v.w = fmaxf(v.w * sc.w + sh.w, 0.f);
            } else if (MODE == 2) {
                if (rootrow) {
                    v.x += rootrow[kg + 0]; v.y += rootrow[kg + 1];
                    v.z += rootrow[kg + 2]; v.w += rootrow[kg + 3];
                }
            }
        } else {
            v = make_float4(0.f, 0.f, 0.f, 0.f);
        }
    };
    auto cpB = [&](int kt, int stage) {
        int goff = b_row * 128 + kt * 8 + b_c * 4;
        uint32_t soff = (stage * STAGE_WORDS + 2 * A_WORDS
                         + b_row * RSTRIDE + b_c * 4) * 4;    // BH region
        cp16(smem_base + soff, Wh + goff);
        cp16(smem_base + soff + B_WORDS * 4, Wl + goff);      // BL region
    };
    auto stsA = [&](int stage, float4 v) {
        uint32_t* AH = dyn + stage * STAGE_WORDS;
        uint32_t* AL = AH + A_WORDS;
        uint32_t h0, l0, h1, l1;
        split2(v.x, v.y, h0, l0);
        split2(v.z, v.w, h1, l1);
        int p = a_row * RSTRIDE + a_kq * 2;
        *(uint2*)(AH + p) = make_uint2(h0, h1);
        *(uint2*)(AL + p) = make_uint2(l0, l1);
    };

    // ---- prologue: prefetch tiles 0 and 1 ----
    ldgA(0, va[0]); cpB(0, 0);
    asm volatile("cp.async.commit_group;" ::: "memory");
    ldgA(1, va[1]); cpB(1, 1);
    asm volatile("cp.async.commit_group;" ::: "memory");
    stsA(0, va[0]);
    asm volatile("cp.async.wait_group 1;" ::: "memory");
    __syncthreads();

    // ldmatrix per-lane offsets (u32 words, within a matrix region)
    const int lm_a = (wm * 32 + (lane & 15)) * RSTRIDE + (lane >> 4) * 4;
    const int lm_b = (wn * 64 + (lane & 15)) * RSTRIDE + (lane >> 4) * 4;

#define MMA(ACC, Af, Bf)                                                      \
    asm volatile(                                                             \
        "mma.sync.aligned.m16n8k16.row.col.f32.bf16.bf16.f32 "                \
        "{%0,%1,%2,%3}, {%4,%5,%6,%7}, {%8,%9}, {%0,%1,%2,%3};"               \
        : "+f"((ACC)[0]), "+f"((ACC)[1]), "+f"((ACC)[2]), "+f"((ACC)[3])      \
        : "r"((Af)[0]), "r"((Af)[1]), "r"((Af)[2]), "r"((Af)[3]),             \
          "r"((Bf)[0]), "r"((Bf)[1]))

#pragma unroll 1
    for (int kt = 0; kt < 16; kt++) {
        const int cur = kt % NSTAGE;

        // prefetch tile kt+2 (A into regs, B via cp.async)
        if (kt < 14) {
            ldgA(kt + 2, va[kt & 1]);
            cpB(kt + 2, (kt + 2) % NSTAGE);
            asm volatile("cp.async.commit_group;" ::: "memory");
        }
        // store A for tile kt+1 (loaded one full iteration ago)
        if (kt < 15) stsA((kt + 1) % NSTAGE, va[(kt + 1) & 1]);

        const uint32_t AH_b = smem_base + (cur * STAGE_WORDS) * 4;
        const uint32_t AL_b = AH_b + A_WORDS * 4;
        const uint32_t BH_b = AL_b + A_WORDS * 4;
        const uint32_t BL_b = BH_b + B_WORDS * 4;

        uint32_t fa[2][4], fb[8][2];

        // phase 1: al . bh
#pragma unroll
        for (int mt = 0; mt < 2; mt++)
            LDMX4(fa[mt][0], fa[mt][1], fa[mt][2], fa[mt][3],
                  AL_b + (lm_a + mt * 16 * RSTRIDE) * 4);
#pragma unroll
        for (int p = 0; p < 4; p++) {
            uint32_t d0, d1, d2, d3;
            LDMX4(d0, d1, d2, d3, BH_b + (lm_b + p * 16 * RSTRIDE) * 4);
            fb[2 * p][0] = d0; fb[2 * p][1] = d2;
            fb[2 * p + 1][0] = d1; fb[2 * p + 1][1] = d3;
        }
#pragma unroll
        for (int mt = 0; mt < 2; mt++)
#pragma unroll
            for (int nt = 0; nt < 8; nt++)
                MMA(acc[mt][nt], fa[mt], fb[nt]);

        // phase 2: ah . bh
        uint32_t fa2[2][4];
#pragma unroll
        for (int mt = 0; mt < 2; mt++)
            LDMX4(fa2[mt][0], fa2[mt][1], fa2[mt][2], fa2[mt][3],
                  AH_b + (lm_a + mt * 16 * RSTRIDE) * 4);
#pragma unroll
        for (int mt = 0; mt < 2; mt++)
#pragma unroll
            for (int nt = 0; nt < 8; nt++)
                MMA(acc[mt][nt], fa2[mt], fb[nt]);

        // phase 3: ah . bl (overwrite fb)
#pragma unroll
        for (int p = 0; p < 4; p++) {
            uint32_t d0, d1, d2, d3;
            LDMX4(d0, d1, d2, d3, BL_b + (lm_b + p * 16 * RSTRIDE) * 4);
            fb[2 * p][0] = d0; fb[2 * p][1] = d2;
            fb[2 * p + 1][0] = d1; fb[2 * p + 1][1] = d3;
        }
#pragma unroll
        for (int mt = 0; mt < 2; mt++)
#pragma unroll
            for (int nt = 0; nt < 8; nt++)
                MMA(acc[mt][nt], fa2[mt], fb[nt]);

        if (kt < 15) {
            if (kt < 14)
                asm volatile("cp.async.wait_group 1;" ::: "memory");
            else
                asm volatile("cp.async.wait_group 0;" ::: "memory");
            __syncthreads();
        }
    }
#undef MMA

    // ---- epilogue: bias add, store, fused column stats ----
#pragma unroll
    for (int nt = 0; nt < 8; nt++) {
        int c = wn * 64 + nt * 8 + (lane & 3) * 2;
        float bv0 = bias[c], bv1 = bias[c + 1];
        float s0 = 0.f, s1 = 0.f, q0 = 0.f, q1 = 0.f;
#pragma unroll
        for (int mt = 0; mt < 2; mt++) {
            int r = m0 + wm * 32 + mt * 16 + (lane >> 2);
#pragma unroll
            for (int hh = 0; hh < 2; hh++) {
                int rr = r + hh * 8;
                if (rr < NN) {
                    float v0 = acc[mt][nt][hh * 2 + 0] + bv0;
                    float v1 = acc[mt][nt][hh * 2 + 1] + bv1;
                    *(float2*)(C + (size_t)rr * HD + c) = make_float2(v0, v1);
                    s0 += v0; s1 += v1;
                    q0 += v0 * v0; q1 += v1 * v1;
                }
            }
        }
#pragma unroll
        for (int o = 4; o < 32; o <<= 1) {
            s0 += __shfl_xor_sync(0xffffffffu, s0, o);
            s1 += __shfl_xor_sync(0xffffffffu, s1, o);
            q0 += __shfl_xor_sync(0xffffffffu, q0, o);
            q1 += __shfl_xor_sync(0xffffffffu, q1, o);
        }
        if ((lane >> 2) == 0) {
            atomicAdd(&s_sum[c],     s0);
            atomicAdd(&s_sum[c + 1], s1);
            atomicAdd(&s_ss[c],      q0);
            atomicAdd(&s_ss[c + 1],  q1);
        }
    }
    __syncthreads();
    if (tid < 256) {
        atomicAdd(&g_sum[tid],   (double)s_sum[tid]);
        atomicAdd(&g_sqsum[tid], (double)s_ss[tid]);
    }
}

// ---------------- residual + LayerNorm: h = LN(h + relu(y2*s+t)) ----------------
// one warp per row, 8 rows per 256-thread block
__global__ void k_resln(const float* __restrict__ y2,
                        const float* __restrict__ lng, const float* __restrict__ lnb) {
    const int w = threadIdx.x >> 5, l = threadIdx.x & 31;
    const int r = blockIdx.x * 8 + w;
    const float4* hrow = (const float4*)(g_h + (size_t)r * HD);
    const float4* yrow = (const float4*)(y2 + (size_t)r * HD);

    float4 u[2];
    float s = 0.f, ss = 0.f;
#pragma unroll
    for (int i = 0; i < 2; i++) {
        int c4 = l + i * 32;
        float4 hv = hrow[c4];
        float4 yv = yrow[c4];
        float4 sc = ((const float4*)g_scale)[c4];
        float4 sh = ((const float4*)g_shift)[c4];
        float4 uu;
        uu.x = hv.x + fmaxf(yv.x * sc.x + sh.x, 0.f);
        uu.y = hv.y + fmaxf(yv.y * sc.y + sh.y, 0.f);
        uu.z = hv.z + fmaxf(yv.z * sc.z + sh.z, 0.f);
        uu.w = hv.w + fmaxf(yv.w * sc.w + sh.w, 0.f);
        u[i] = uu;
        s  += uu.x + uu.y + uu.z + uu.w;
        ss += uu.x * uu.x + uu.y * uu.y + uu.z * uu.z + uu.w * uu.w;
    }
#pragma unroll
    for (int o = 16; o > 0; o >>= 1) {
        s  += __shfl_xor_sync(0xffffffffu, s, o);
        ss += __shfl_xor_sync(0xffffffffu, ss, o);
    }
    float mean = s * (1.f / HD);
    float var = ss * (1.f / HD) - mean * mean;
    if (var < 0.f) var = 0.f;
    float rs = rsqrtf(var + LN_EPS);

    float4* orow = (float4*)(g_h + (size_t)r * HD);
#pragma unroll
    for (int i = 0; i < 2; i++) {
        int c4 = l + i * 32;
        float4 gg = ((const float4*)lng)[c4];
        float4 bb = ((const float4*)lnb)[c4];
        float4 uu = u[i];
        float4 o4;
        o4.x = gg.x * (uu.x - mean) * rs + bb.x;
        o4.y = gg.y * (uu.y - mean) * rs + bb.y;
        o4.z = gg.z * (uu.z - mean) * rs + bb.z;
        o4.w = gg.w * (uu.w - mean) * rs + bb.w;
        orow[c4] = o4;
    }
}

// ---------------- readout: out[g,o] = h[root_g] . Wout[o] ----------------
__global__ void k_out(const float* __restrict__ Wout, float* __restrict__ out) {
    int g = blockIdx.x;
    int w = threadIdx.x >> 5;
    int l = threadIdx.x & 31;
    const float* hr = g_h + (size_t)g * TREE_TOTAL * HD;
    const float* wr = Wout + (size_t)w * HD;
    float s = 0.f;
#pragma unroll
    for (int k = l; k < HD; k += 32) s += hr[k] * wr[k];
#pragma unroll
    for (int o = 16; o > 0; o >>= 1) s += __shfl_down_sync(0xffffffffu, s, o);
    if (l == 0) out[g * 32 + w] = s;
}

// ---------------- launch ----------------
extern "C" void kernel_launch(void* const* d_in, const int* in_sizes, int n_in,
                              void* d_out, int out_size) {
    const int*   x    = (const int*)d_in[0];
    const int*   esrc = (const int*)d_in[1];
    const int*   edst = (const int*)d_in[2];
    const float* ew   = (const float*)d_in[3];
    const float* en   = (const float*)d_in[6];
    const float* el   = (const float*)d_in[7];
    const float* W1   = (const float*)d_in[8];
    const float* b1   = (const float*)d_in[9];
    const float* g1   = (const float*)d_in[10];
    const float* be1  = (const float*)d_in[11];
    const float* W2   = (const float*)d_in[12];
    const float* b2   = (const float*)d_in[13];
    const float* g2   = (const float*)d_in[14];
    const float* be2  = (const float*)d_in[15];
    const float* lng  = (const float*)d_in[16];
    const float* lnb  = (const float*)d_in[17];
    const float* Wout = (const float*)d_in[18];
    float* out = (float*)d_out;

    float *h, *agg, *y1, *y2, *root;
    uint32_t *Wh, *Wl;
    cudaGetSymbolAddress((void**)&h,    g_h);
    cudaGetSymbolAddress((void**)&agg,  g_agg);
    cudaGetSymbolAddress((void**)&y1,   g_y1);
    cudaGetSymbolAddress((void**)&y2,   g_y2);
    cudaGetSymbolAddress((void**)&root, g_root);
    cudaGetSymbolAddress((void**)&Wh,   g_Wh);
    cudaGetSymbolAddress((void**)&Wl,   g_Wl);

    cudaFuncSetAttribute(k_gemm_tc<0>, cudaFuncAttributeMaxDynamicSharedMemorySize, SMEM_BYTES);
    cudaFuncSetAttribute(k_gemm_tc<1>, cudaFuncAttributeMaxDynamicSharedMemorySize, SMEM_BYTES);
    cudaFuncSetAttribute(k_gemm_tc<2>, cudaFuncAttributeMaxDynamicSharedMemorySize, SMEM_BYTES);

    const int ggrid = (NN + 127) / 128;   // 1024

    k_splitW<<<(8 * 256 * 128) / 256, 256>>>(W1, W2);
    k_embed<<<(NN * 64) / 256, 256>>>(x, en, el);

    for (int i = 0; i < NL; i++) {
        const uint32_t* Wh1 = Wh + (size_t)i * 32768;
        const uint32_t* Wl1 = Wl + (size_t)i * 32768;
        const uint32_t* Wh2 = Wh + (size_t)(i + 4) * 32768;
        const uint32_t* Wl2 = Wl + (size_t)(i + 4) * 32768;
        const float* b1i = b1 + i * HD;
        const float* b2i = b2 + i * HD;
        const float* g1i = g1 + i * HD;
        const float* g2i = g2 + i * HD;
        const float* be1i = be1 + i * HD;
        const float* be2i = be2 + i * HD;
        const float* lngi = lng + i * HD;
        const float* lnbi = lnb + i * HD;

        if (i < NL - 1) {
            cudaMemsetAsync(agg, 0, (size_t)NN * HD * sizeof(float));
            k_scatter<<<(NE * 64) / 256, 256>>>(esrc, edst, ew);
            k_gemm_tc<0><<<ggrid, 512, SMEM_BYTES>>>(h, agg, Wh1, Wl1, b1i, y1);
        } else {
            cudaMemsetAsync(root, 0, (size_t)NG * HD * sizeof(float));
            k_rootsum<<<dim3(NG, 8), 256>>>();
            k_gemm_tc<2><<<ggrid, 512, SMEM_BYTES>>>(h, nullptr, Wh1, Wl1, b1i, y1);
        }
        k_makescale<<<1, 256>>>(g1i, be1i);
        k_gemm_tc<1><<<ggrid, 512, SMEM_BYTES>>>(y1, nullptr, Wh2, Wl2, b2i, y2);
        k_makescale<<<1, 256>>>(g2i, be2i);
        k_resln<<<NN / 8, 256>>>(y2, lngi, lnbi);
    }

    k_out<<<NG, 1024>>>(Wout, out);
}

// round 16
// speedup vs baseline: 1.0150x; 1.0150x over previous
#include <cuda_runtime.h>
#include <math.h>
#include <stdint.h>

#define TREE_TOTAL 2047
#define NG 64
#define NN (NG * TREE_TOTAL)      // 131008
#define NE (2 * NN)               // 262016
#define HD 256
#define HALF 128
#define NL 4
#define BN_EPS 1e-5f
#define LN_EPS 1e-5f

// ---------------- scratch (no allocation allowed) ----------------
__device__ float  g_h  [(size_t)NN * HD];
__device__ float  g_agg[(size_t)NN * HD];
__device__ float  g_y1 [(size_t)NN * HD];
__device__ float  g_y2 [(size_t)NN * HD];
__device__ float  g_root[NG * HD];
__device__ double g_sum [HD];     // zero-init; k_makescale re-zeroes after use
__device__ double g_sqsum[HD];
__device__ float  g_scale[HD];
__device__ float  g_shift[HD];
// pre-split weights: 8 matrices (W1 x4, W2 x4), [mat][row][kpair] bf16x2 words
__device__ uint32_t g_Wh[8 * 256 * 128];
__device__ uint32_t g_Wl[8 * 256 * 128];
// in-edge CSR (rebuilt every launch)
__device__ int g_cnt[NN];
__device__ int g_off[NN + 1];
__device__ int g_cur[NN];
__device__ int g_eidx[NE];

// split two floats (even k, odd k) into hi/lo bf16x2 packed words
__device__ __forceinline__ void split2(float e, float o, uint32_t& hi, uint32_t& lo) {
    uint32_t h;
    asm("cvt.rn.bf16x2.f32 %0, %1, %2;" : "=r"(h) : "f"(o), "f"(e));
    float ef = __uint_as_float(h << 16);
    float of = __uint_as_float(h & 0xffff0000u);
    float re = e - ef;
    float ro = o - of;
    uint32_t l;
    asm("cvt.rn.bf16x2.f32 %0, %1, %2;" : "=r"(l) : "f"(ro), "f"(re));
    hi = h; lo = l;
}

// ---------------- pre-split all weight matrices ----------------
__global__ void k_splitW(const float* __restrict__ W1, const float* __restrict__ W2) {
    int idx = blockIdx.x * blockDim.x + threadIdx.x;   // 8*256*128
    if (idx >= 8 * 256 * 128) return;
    int p = idx & 127;          // kpair
    int r = (idx >> 7) & 255;   // row (output-n)
    int m = idx >> 15;          // matrix 0..7
    const float* W = (m < 4) ? (W1 + (size_t)m * HD * HD)
                             : (W2 + (size_t)(m - 4) * HD * HD);
    float e = W[r * HD + 2 * p];
    float o = W[r * HD + 2 * p + 1];
    uint32_t h, l;
    split2(e, o, h, l);
    g_Wh[idx] = h;
    g_Wl[idx] = l;
}

// ---------------- embedding: h = concat(emb_node[x0], emb_label[x1]) ----------------
__global__ void k_embed(const int* __restrict__ x,
                        const float* __restrict__ en,
                        const float* __restrict__ el) {
    int idx = blockIdx.x * blockDim.x + threadIdx.x;
    if (idx >= NN * 64) return;
    int n = idx >> 6, q = idx & 63;
    float4 v;
    if (q < 32) {
        int e = x[2 * n];
        v = ((const float4*)(en + (size_t)e * HALF))[q];
    } else {
        int e = x[2 * n + 1];
        v = ((const float4*)(el + (size_t)e * HALF))[q - 32];
    }
    ((float4*)(g_h + (size_t)n * HD))[q] = v;
}

// ---------------- CSR build: count / scan / fill ----------------
__global__ void k_count(const int* __restrict__ dst) {
    int e = blockIdx.x * blockDim.x + threadIdx.x;
    if (e < NE) atomicAdd(&g_cnt[dst[e]], 1);
}

__global__ void k_scan() {
    __shared__ int psum[1024];
    const int t = threadIdx.x;
    const int base = t * 128;
    int s = 0;
    for (int i = 0; i < 128; i++) {
        int idx = base + i;
        if (idx < NN) s += g_cnt[idx];
    }
    psum[t] = s;
    __syncthreads();
    for (int o = 1; o < 1024; o <<= 1) {
        int v = 0;
        if (t >= o) v = psum[t - o];
        __syncthreads();
        if (t >= o) psum[t] += v;
        __syncthreads();
    }
    int run = (t == 0) ? 0 : psum[t - 1];
    for (int i = 0; i < 128; i++) {
        int idx = base + i;
        if (idx < NN) {
            g_off[idx] = run;
            g_cur[idx] = run;
            run += g_cnt[idx];
        }
    }
    if (t == 1023) g_off[NN] = run;
}

__global__ void k_fill(const int* __restrict__ dst) {
    int e = blockIdx.x * blockDim.x + threadIdx.x;
    if (e < NE) {
        int p = atomicAdd(&g_cur[dst[e]], 1);
        g_eidx[p] = e;
    }
}

// ---------------- pull-gather: agg[n] = sum_in-edges h[src] * w ----------------
// one warp covers one half-row (32 float4s of a node); in-edge loop is
// warp-uniform (all lanes share n).
__global__ void k_gather(const int* __restrict__ src, const float* __restrict__ w) {
    int idx = blockIdx.x * blockDim.x + threadIdx.x;   // NN*64
    int n = idx >> 6, q = idx & 63;
    int j0 = g_off[n], j1 = g_off[n + 1];
    float4 acc = make_float4(0.f, 0.f, 0.f, 0.f);
    for (int j = j0; j < j1; j++) {
        int e = g_eidx[j];
        int s = src[e];
        float ww = w[e];
        float4 v = ((const float4*)(g_h + (size_t)s * HD))[q];
        acc.x += v.x * ww; acc.y += v.y * ww;
        acc.z += v.z * ww; acc.w += v.w * ww;
    }
    ((float4*)(g_agg + (size_t)n * HD))[q] = acc;
}

// ---------------- last layer: per-graph sum of all node features ----------------
__global__ void k_rootsum() {
    int g = blockIdx.x;
    int c = blockIdx.y;
    int t = threadIdx.x;
    int r0 = c * 256;
    int r1 = r0 + 256; if (r1 > TREE_TOTAL) r1 = TREE_TOTAL;
    float s = 0.f;
    const float* base = g_h + ((size_t)g * TREE_TOTAL) * HD + t;
    for (int r = r0; r < r1; r++) s += base[(size_t)r * HD];
    atomicAdd(&g_root[g * HD + t], s);
}

// ---------------- BN -> per-column scale/shift; re-zero stats ----------------
__global__ void k_makescale(const float* __restrict__ gamma, const float* __restrict__ beta) {
    int t = threadIdx.x;
    double m = g_sum[t] / (double)NN;
    double v = g_sqsum[t] / (double)NN - m * m;
    if (v < 0.0) v = 0.0;
    double rs = 1.0 / sqrt(v + (double)BN_EPS);
    float sc = gamma[t] * (float)rs;
    g_scale[t] = sc;
    g_shift[t] = beta[t] - (float)m * sc;
    g_sum[t] = 0.0;
    g_sqsum[t] = 0.0;
}

// ============================================================================
// BF16x3 tensor-core GEMM, full-width tiles: C[128,256] per CTA, grid = 1024.
// (exact round-11 champion configuration)
// B (weights) pre-split in global -> cp.async straight into smem (no regs).
// A transformed + split in registers (mode-dependent).
// 512 threads, 16 warps (4m x 4n), warp tile 32x64, BK=16, double-buffered.
// MODE 0: a = A1 + A2
// MODE 1: a = relu(A1 * g_scale[k] + g_shift[k])
// MODE 2: a = A1 + (row % 2047 == 0 ? g_root[row/2047] : 0)
// ============================================================================
#define GPA 136                     // A smem row stride (u32)
#define A_WORDS (8 * GPA)           // 1088 per matrix
#define BROW 12                     // B smem row stride (u32), 48B (16B aligned)
#define B_WORDS (256 * BROW)        // 3072 per matrix
#define STAGE_WORDS (2 * A_WORDS + 2 * B_WORDS)   // 8320
#define STATS_OFF (2 * STAGE_WORDS)               // 16640
#define SMEM_WORDS (STATS_OFF + 512)
#define SMEM_BYTES (SMEM_WORDS * 4)               // 68608

__device__ __forceinline__ void cp16(uint32_t saddr, const void* gptr) {
    asm volatile("cp.async.cg.shared.global [%0], [%1], 16;"
                 :: "r"(saddr), "l"(gptr) : "memory");
}

template <int MODE>
__global__ void __launch_bounds__(512, 1)
k_gemm_tc(const float* __restrict__ A1, const float* __restrict__ A2,
          const uint32_t* __restrict__ Wh, const uint32_t* __restrict__ Wl,
          const float* __restrict__ bias, float* __restrict__ C) {
    extern __shared__ uint32_t dyn[];
    float* s_sum = (float*)(dyn + STATS_OFF);
    float* s_ss  = (float*)(dyn + STATS_OFF + 256);
    const uint32_t smem_base = (uint32_t)__cvta_generic_to_shared(dyn);

    const int m0 = blockIdx.x * 128;
    const int tid = threadIdx.x;
    const int lane = tid & 31;
    const int warp = tid >> 5;
    const int wm = warp & 3;        // 32-row slab
    const int wn = warp >> 2;       // 64-col slab

    // A loader: 1 float4 per K-tile
    const int a_row = tid >> 2;     // 0..127
    const int a_kq  = tid & 3;      // float4 within 16-wide k
    // B loader: 16B hi + 16B lo per thread
    const int b_row = tid >> 1;     // 0..255
    const int b_c   = tid & 1;      // half-row chunk

    const int grow = m0 + a_row;
    const bool rok = grow < NN;
    const float* rootrow = nullptr;
    if (MODE == 2 && rok && (grow % TREE_TOTAL) == 0)
        rootrow = g_root + (grow / TREE_TOTAL) * HD;

    if (tid < 256) { s_sum[tid] = 0.f; s_ss[tid] = 0.f; }

    float acc[2][8][4];
#pragma unroll
    for (int i = 0; i < 2; i++)
#pragma unroll
        for (int j = 0; j < 8; j++)
#pragma unroll
            for (int q = 0; q < 4; q++) acc[i][j][q] = 0.f;

    float4 va;

    auto ldgA = [&](int kt) {
        int kg = kt * 16 + a_kq * 4;
        if (rok) {
            va = *(const float4*)(A1 + (size_t)grow * HD + kg);
            if (MODE == 0) {
                float4 w4 = *(const float4*)(A2 + (size_t)grow * HD + kg);
                va.x += w4.x; va.y += w4.y; va.z += w4.z; va.w += w4.w;
            } else if (MODE == 1) {
                float4 sc = *(const float4*)(g_scale + kg);
                float4 sh = *(const float4*)(g_shift + kg);
                va.x = fmaxf(va.x * sc.x + sh.x, 0.f);
                va.y = fmaxf(va.y * sc.y + sh.y, 0.f);
                va.z = fmaxf(va.z * sc.z + sh.z, 0.f);
                va.w = fmaxf(va.w * sc.w + sh.w, 0.f);
            } else if (MODE == 2) {
                if (rootrow) {
                    va.x += rootrow[kg + 0]; va.y += rootrow[kg + 1];
                    va.z += rootrow[kg + 2]; va.w += rootrow[kg + 3];
                }
            }
        } else {
            va = make_float4(0.f, 0.f, 0.f, 0.f);
        }
    };
    auto cpB = [&](int kt, int stage) {
        int goff = b_row * 128 + kt * 8 + b_c * 4;
        uint32_t soff = (stage * STAGE_WORDS + 2 * A_WORDS
                         + b_row * BROW + b_c * 4) * 4;  // byte offset, BH region
        cp16(smem_base + soff, Wh + goff);
        cp16(smem_base + soff + B_WORDS * 4, Wl + goff); // BL region
    };
    auto stsA = [&](int stage) {
        uint32_t* AH = dyn + stage * STAGE_WORDS;
        uint32_t* AL = AH + A_WORDS;
        uint32_t h0, l0, h1, l1;
        int p0 = (a_kq * 2) * GPA + a_row;
        int p1 = (a_kq * 2 + 1) * GPA + a_row;
        split2(va.x, va.y, h0, l0);
        split2(va.z, va.w, h1, l1);
        AH[p0] = h0; AH[p1] = h1;
        AL[p0] = l0; AL[p1] = l1;
    };

    // prologue
    ldgA(0);
    cpB(0, 0);
    asm volatile("cp.async.commit_group;" ::: "memory");
    stsA(0);
    asm volatile("cp.async.wait_group 0;" ::: "memory");
    __syncthreads();

    const int kl = lane & 3;
    const int rbase = wm * 32 + (lane >> 2);
    const int nbase = wn * 64 + (lane >> 2);

#define MMA(ACC, Af, Bf)                                                      \
    asm volatile(                                                             \
        "mma.sync.aligned.m16n8k16.row.col.f32.bf16.bf16.f32 "                \
        "{%0,%1,%2,%3}, {%4,%5,%6,%7}, {%8,%9}, {%0,%1,%2,%3};"               \
        : "+f"((ACC)[0]), "+f"((ACC)[1]), "+f"((ACC)[2]), "+f"((ACC)[3])      \
        : "r"((Af)[0]), "r"((Af)[1]), "r"((Af)[2]), "r"((Af)[3]),             \
          "r"((Bf)[0]), "r"((Bf)[1]))

#pragma unroll 1
    for (int kt = 0; kt < 16; kt++) {
        const int cur = kt & 1;
        if (kt < 15) {
            ldgA(kt + 1);
            cpB(kt + 1, cur ^ 1);
            asm volatile("cp.async.commit_group;" ::: "memory");
        }

        const uint32_t* AH = dyn + cur * STAGE_WORDS;
        const uint32_t* AL = AH + A_WORDS;
        const uint32_t* BH = AL + A_WORDS;
        const uint32_t* BL = BH + B_WORDS;

        // phase 1: al . bh
        uint32_t fa[2][4], fb[8][2];
#pragma unroll
        for (int mt = 0; mt < 2; mt++) {
            int r = rbase + mt * 16;
            fa[mt][0] = AL[kl * GPA + r];
            fa[mt][1] = AL[kl * GPA + r + 8];
            fa[mt][2] = AL[(kl + 4) * GPA + r];
            fa[mt][3] = AL[(kl + 4) * GPA + r + 8];
        }
#pragma unroll
        for (int nt = 0; nt < 8; nt++) {
            int n = nbase + nt * 8;
            fb[nt][0] = BH[n * BROW + kl];
            fb[nt][1] = BH[n * BROW + kl + 4];
        }
#pragma unroll
        for (int mt = 0; mt < 2; mt++)
#pragma unroll
            for (int nt = 0; nt < 8; nt++)
                MMA(acc[mt][nt], fa[mt], fb[nt]);

        // phase 2: ah . bh
        uint32_t fa2[2][4];
#pragma unroll
        for (int mt = 0; mt < 2; mt++) {
            int r = rbase + mt * 16;
            fa2[mt][0] = AH[kl * GPA + r];
            fa2[mt][1] = AH[kl * GPA + r + 8];
            fa2[mt][2] = AH[(kl + 4) * GPA + r];
            fa2[mt][3] = AH[(kl + 4) * GPA + r + 8];
        }
#pragma unroll
        for (int mt = 0; mt < 2; mt++)
#pragma unroll
            for (int nt = 0; nt < 8; nt++)
                MMA(acc[mt][nt], fa2[mt], fb[nt]);

        // phase 3: ah . bl (overwrite fb)
#pragma unroll
        for (int nt = 0; nt < 8; nt++) {
            int n = nbase + nt * 8;
            fb[nt][0] = BL[n * BROW + kl];
            fb[nt][1] = BL[n * BROW + kl + 4];
        }
#pragma unroll
        for (int mt = 0; mt < 2; mt++)
#pragma unroll
            for (int nt = 0; nt < 8; nt++)
                MMA(acc[mt][nt], fa2[mt], fb[nt]);

        if (kt < 15) {
            stsA(cur ^ 1);
            asm volatile("cp.async.wait_group 0;" ::: "memory");
            __syncthreads();
        }
    }
#undef MMA

    // ---- epilogue: bias add, store, fused column stats ----
#pragma unroll
    for (int nt = 0; nt < 8; nt++) {
        int c = wn * 64 + nt * 8 + (lane & 3) * 2;
        float bv0 = bias[c], bv1 = bias[c + 1];
        float s0 = 0.f, s1 = 0.f, q0 = 0.f, q1 = 0.f;
#pragma unroll
        for (int mt = 0; mt < 2; mt++) {
            int r = m0 + wm * 32 + mt * 16 + (lane >> 2);
#pragma unroll
            for (int hh = 0; hh < 2; hh++) {
                int rr = r + hh * 8;
                if (rr < NN) {
                    float v0 = acc[mt][nt][hh * 2 + 0] + bv0;
                    float v1 = acc[mt][nt][hh * 2 + 1] + bv1;
                    *(float2*)(C + (size_t)rr * HD + c) = make_float2(v0, v1);
                    s0 += v0; s1 += v1;
                    q0 += v0 * v0; q1 += v1 * v1;
                }
            }
        }
#pragma unroll
        for (int o = 4; o < 32; o <<= 1) {
            s0 += __shfl_xor_sync(0xffffffffu, s0, o);
            s1 += __shfl_xor_sync(0xffffffffu, s1, o);
            q0 += __shfl_xor_sync(0xffffffffu, q0, o);
            q1 += __shfl_xor_sync(0xffffffffu, q1, o);
        }
        if ((lane >> 2) == 0) {
            atomicAdd(&s_sum[c],     s0);
            atomicAdd(&s_sum[c + 1], s1);
            atomicAdd(&s_ss[c],      q0);
            atomicAdd(&s_ss[c + 1],  q1);
        }
    }
    __syncthreads();
    if (tid < 256) {
        atomicAdd(&g_sum[tid],   (double)s_sum[tid]);
        atomicAdd(&g_sqsum[tid], (double)s_ss[tid]);
    }
}

// ---------------- residual + LayerNorm: h = LN(h + relu(y2*s+t)) ----------------
// one warp per row, 8 rows per 256-thread block
__global__ void k_resln(const float* __restrict__ y2,
                        const float* __restrict__ lng, const float* __restrict__ lnb) {
    const int w = threadIdx.x >> 5, l = threadIdx.x & 31;
    const int r = blockIdx.x * 8 + w;
    const float4* hrow = (const float4*)(g_h + (size_t)r * HD);
    const float4* yrow = (const float4*)(y2 + (size_t)r * HD);

    float4 u[2];
    float s = 0.f, ss = 0.f;
#pragma unroll
    for (int i = 0; i < 2; i++) {
        int c4 = l + i * 32;
        float4 hv = hrow[c4];
        float4 yv = yrow[c4];
        float4 sc = ((const float4*)g_scale)[c4];
        float4 sh = ((const float4*)g_shift)[c4];
        float4 uu;
        uu.x = hv.x + fmaxf(yv.x * sc.x + sh.x, 0.f);
        uu.y = hv.y + fmaxf(yv.y * sc.y + sh.y, 0.f);
        uu.z = hv.z + fmaxf(yv.z * sc.z + sh.z, 0.f);
        uu.w = hv.w + fmaxf(yv.w * sc.w + sh.w, 0.f);
        u[i] = uu;
        s  += uu.x + uu.y + uu.z + uu.w;
        ss += uu.x * uu.x + uu.y * uu.y + uu.z * uu.z + uu.w * uu.w;
    }
#pragma unroll
    for (int o = 16; o > 0; o >>= 1) {
        s  += __shfl_xor_sync(0xffffffffu, s, o);
        ss += __shfl_xor_sync(0xffffffffu, ss, o);
    }
    float mean = s * (1.f / HD);
    float var = ss * (1.f / HD) - mean * mean;
    if (var < 0.f) var = 0.f;
    float rs = rsqrtf(var + LN_EPS);

    float4* orow = (float4*)(g_h + (size_t)r * HD);
#pragma unroll
    for (int i = 0; i < 2; i++) {
        int c4 = l + i * 32;
        float4 gg = ((const float4*)lng)[c4];
        float4 bb = ((const float4*)lnb)[c4];
        float4 uu = u[i];
        float4 o4;
        o4.x = gg.x * (uu.x - mean) * rs + bb.x;
        o4.y = gg.y * (uu.y - mean) * rs + bb.y;
        o4.z = gg.z * (uu.z - mean) * rs + bb.z;
        o4.w = gg.w * (uu.w - mean) * rs + bb.w;
        orow[c4] = o4;
    }
}

// ---------------- readout: out[g,o] = h[root_g] . Wout[o] ----------------
__global__ void k_out(const float* __restrict__ Wout, float* __restrict__ out) {
    int g = blockIdx.x;
    int w = threadIdx.x >> 5;
    int l = threadIdx.x & 31;
    const float* hr = g_h + (size_t)g * TREE_TOTAL * HD;
    const float* wr = Wout + (size_t)w * HD;
    float s = 0.f;
#pragma unroll
    for (int k = l; k < HD; k += 32) s += hr[k] * wr[k];
#pragma unroll
    for (int o = 16; o > 0; o >>= 1) s += __shfl_down_sync(0xffffffffu, s, o);
    if (l == 0) out[g * 32 + w] = s;
}

// ---------------- launch ----------------
extern "C" void kernel_launch(void* const* d_in, const int* in_sizes, int n_in,
                              void* d_out, int out_size) {
    const int*   x    = (const int*)d_in[0];
    const int*   esrc = (const int*)d_in[1];
    const int*   edst = (const int*)d_in[2];
    const float* ew   = (const float*)d_in[3];
    const float* en   = (const float*)d_in[6];
    const float* el   = (const float*)d_in[7];
    const float* W1   = (const float*)d_in[8];
    const float* b1   = (const float*)d_in[9];
    const float* g1   = (const float*)d_in[10];
    const float* be1  = (const float*)d_in[11];
    const float* W2   = (const float*)d_in[12];
    const float* b2   = (const float*)d_in[13];
    const float* g2   = (const float*)d_in[14];
    const float* be2  = (const float*)d_in[15];
    const float* lng  = (const float*)d_in[16];
    const float* lnb  = (const float*)d_in[17];
    const float* Wout = (const float*)d_in[18];
    float* out = (float*)d_out;

    float *h, *agg, *y1, *y2, *root;
    uint32_t *Wh, *Wl;
    int* cnt;
    cudaGetSymbolAddress((void**)&h,    g_h);
    cudaGetSymbolAddress((void**)&agg,  g_agg);
    cudaGetSymbolAddress((void**)&y1,   g_y1);
    cudaGetSymbolAddress((void**)&y2,   g_y2);
    cudaGetSymbolAddress((void**)&root, g_root);
    cudaGetSymbolAddress((void**)&Wh,   g_Wh);
    cudaGetSymbolAddress((void**)&Wl,   g_Wl);
    cudaGetSymbolAddress((void**)&cnt,  g_cnt);

    cudaFuncSetAttribute(k_gemm_tc<0>, cudaFuncAttributeMaxDynamicSharedMemorySize, SMEM_BYTES);
    cudaFuncSetAttribute(k_gemm_tc<1>, cudaFuncAttributeMaxDynamicSharedMemorySize, SMEM_BYTES);
    cudaFuncSetAttribute(k_gemm_tc<2>, cudaFuncAttributeMaxDynamicSharedMemorySize, SMEM_BYTES);

    const int ggrid = (NN + 127) / 128;   // 1024

    // per-launch CSR build (in-edges by destination)
    cudaMemsetAsync(cnt, 0, NN * sizeof(int));
    k_splitW<<<(8 * 256 * 128) / 256, 256>>>(W1, W2);
    k_embed<<<(NN * 64) / 256, 256>>>(x, en, el);
    k_count<<<(NE + 255) / 256, 256>>>(edst);
    k_scan<<<1, 1024>>>();
    k_fill<<<(NE + 255) / 256, 256>>>(edst);

    for (int i = 0; i < NL; i++) {
        const uint32_t* Wh1 = Wh + (size_t)i * 32768;
        const uint32_t* Wl1 = Wl + (size_t)i * 32768;
        const uint32_t* Wh2 = Wh + (size_t)(i + 4) * 32768;
        const uint32_t* Wl2 = Wl + (size_t)(i + 4) * 32768;
        const float* b1i = b1 + i * HD;
        const float* b2i = b2 + i * HD;
        const float* g1i = g1 + i * HD;
        const float* g2i = g2 + i * HD;
        const float* be1i = be1 + i * HD;
        const float* be2i = be2 + i * HD;
        const float* lngi = lng + i * HD;
        const float* lnbi = lnb + i * HD;

        if (i < NL - 1) {
            k_gather<<<(NN * 64) / 256, 256>>>(esrc, ew);
            k_gemm_tc<0><<<ggrid, 512, SMEM_BYTES>>>(h, agg, Wh1, Wl1, b1i, y1);
        } else {
            cudaMemsetAsync(root, 0, (size_t)NG * HD * sizeof(float));
            k_rootsum<<<dim3(NG, 8), 256>>>();
            k_gemm_tc<2><<<ggrid, 512, SMEM_BYTES>>>(h, nullptr, Wh1, Wl1, b1i, y1);
        }
        k_makescale<<<1, 256>>>(g1i, be1i);
        k_gemm_tc<1><<<ggrid, 512, SMEM_BYTES>>>(y1, nullptr, Wh2, Wl2, b2i, y2);
        k_makescale<<<1, 256>>>(g2i, be2i);
        k_resln<<<NN / 8, 256>>>(y2, lngi, lnbi);
    }

    k_out<<<NG, 1024>>>(Wout, out);
}

// round 17
// speedup vs baseline: 1.1516x; 1.1346x over previous
#include <cuda_runtime.h>
#include <math.h>
#include <stdint.h>

#define TREE_TOTAL 2047
#define NG 64
#define NN (NG * TREE_TOTAL)      // 131008
#define NE (2 * NN)               // 262016
#define HD 256
#define HALF 128
#define NL 4
#define BN_EPS 1e-5f
#define LN_EPS 1e-5f

// ---------------- scratch (no allocation allowed) ----------------
__device__ float  g_h  [(size_t)NN * HD];
__device__ float  g_agg[(size_t)NN * HD];
__device__ float  g_y1 [(size_t)NN * HD];
__device__ float  g_y2 [(size_t)NN * HD];
__device__ float  g_root[NG * HD];
__device__ double g_sum [HD];     // zero-init; k_makescale re-zeroes after use
__device__ double g_sqsum[HD];
__device__ float  g_scale[HD];
__device__ float  g_shift[HD];
// pre-split weights: 8 matrices (W1 x4, W2 x4), [mat][row][kpair] bf16x2 words
__device__ uint32_t g_Wh[8 * 256 * 128];
__device__ uint32_t g_Wl[8 * 256 * 128];
// in-edge CSR (rebuilt every launch)
__device__ int g_cnt[NN];
__device__ int g_off[NN + 1];
__device__ int g_cur[NN];
__device__ int g_eidx[NE];
__device__ int g_bsum[512];

// split two floats (even k, odd k) into hi/lo bf16x2 packed words
__device__ __forceinline__ void split2(float e, float o, uint32_t& hi, uint32_t& lo) {
    uint32_t h;
    asm("cvt.rn.bf16x2.f32 %0, %1, %2;" : "=r"(h) : "f"(o), "f"(e));
    float ef = __uint_as_float(h << 16);
    float of = __uint_as_float(h & 0xffff0000u);
    float re = e - ef;
    float ro = o - of;
    uint32_t l;
    asm("cvt.rn.bf16x2.f32 %0, %1, %2;" : "=r"(l) : "f"(ro), "f"(re));
    hi = h; lo = l;
}

// ---------------- pre-split all weight matrices ----------------
__global__ void k_splitW(const float* __restrict__ W1, const float* __restrict__ W2) {
    int idx = blockIdx.x * blockDim.x + threadIdx.x;   // 8*256*128
    if (idx >= 8 * 256 * 128) return;
    int p = idx & 127;          // kpair
    int r = (idx >> 7) & 255;   // row (output-n)
    int m = idx >> 15;          // matrix 0..7
    const float* W = (m < 4) ? (W1 + (size_t)m * HD * HD)
                             : (W2 + (size_t)(m - 4) * HD * HD);
    float e = W[r * HD + 2 * p];
    float o = W[r * HD + 2 * p + 1];
    uint32_t h, l;
    split2(e, o, h, l);
    g_Wh[idx] = h;
    g_Wl[idx] = l;
}

// ---------------- embedding: h = concat(emb_node[x0], emb_label[x1]) ----------------
__global__ void k_embed(const int* __restrict__ x,
                        const float* __restrict__ en,
                        const float* __restrict__ el) {
    int idx = blockIdx.x * blockDim.x + threadIdx.x;
    if (idx >= NN * 64) return;
    int n = idx >> 6, q = idx & 63;
    float4 v;
    if (q < 32) {
        int e = x[2 * n];
        v = ((const float4*)(en + (size_t)e * HALF))[q];
    } else {
        int e = x[2 * n + 1];
        v = ((const float4*)(el + (size_t)e * HALF))[q - 32];
    }
    ((float4*)(g_h + (size_t)n * HD))[q] = v;
}

// ---------------- CSR build: count / 3-phase scan / fill ----------------
__global__ void k_count(const int* __restrict__ dst) {
    int e = blockIdx.x * blockDim.x + threadIdx.x;
    if (e < NE) atomicAdd(&g_cnt[dst[e]], 1);
}

// per-block scan (512 blocks x 256): local exclusive offsets + block totals
__global__ void k_scan1() {
    int i = blockIdx.x * 256 + threadIdx.x;
    int v = (i < NN) ? g_cnt[i] : 0;
    int lane = threadIdx.x & 31, wid = threadIdx.x >> 5;
    int inc = v;
#pragma unroll
    for (int o = 1; o < 32; o <<= 1) {
        int t = __shfl_up_sync(0xffffffffu, inc, o);
        if (lane >= o) inc += t;
    }
    __shared__ int wsum[8];
    if (lane == 31) wsum[wid] = inc;
    __syncthreads();
    if (wid == 0) {
        int ws = (lane < 8) ? wsum[lane] : 0;
#pragma unroll
        for (int o = 1; o < 8; o <<= 1) {
            int t = __shfl_up_sync(0xffffffffu, ws, o);
            if (lane >= o) ws += t;
        }
        if (lane < 8) wsum[lane] = ws;
    }
    __syncthreads();
    int wofs = (wid > 0) ? wsum[wid - 1] : 0;
    if (i < NN) g_off[i] = wofs + inc - v;     // block-local exclusive
    if (threadIdx.x == 255) g_bsum[blockIdx.x] = wsum[7];
}

// scan the 512 block totals (1 block x 512)
__global__ void k_scan2() {
    int t = threadIdx.x;
    int v = g_bsum[t];
    int lane = t & 31, wid = t >> 5;
    int inc = v;
#pragma unroll
    for (int o = 1; o < 32; o <<= 1) {
        int x2 = __shfl_up_sync(0xffffffffu, inc, o);
        if (lane >= o) inc += x2;
    }
    __shared__ int wsum[16];
    if (lane == 31) wsum[wid] = inc;
    __syncthreads();
    if (wid == 0) {
        int ws = (lane < 16) ? wsum[lane] : 0;
#pragma unroll
        for (int o = 1; o < 16; o <<= 1) {
            int x2 = __shfl_up_sync(0xffffffffu, ws, o);
            if (lane >= o) ws += x2;
        }
        if (lane < 16) wsum[lane] = ws;
    }
    __syncthreads();
    int wofs = (wid > 0) ? wsum[wid - 1] : 0;
    g_bsum[t] = wofs + inc - v;                // exclusive block offset
}

// add block offsets; init g_cur; total is the constant NE
__global__ void k_scan3() {
    int i = blockIdx.x * 256 + threadIdx.x;
    if (i < NN) {
        int o = g_off[i] + g_bsum[blockIdx.x];
        g_off[i] = o;
        g_cur[i] = o;
    }
    if (i == 0) g_off[NN] = NE;
}

__global__ void k_fill(const int* __restrict__ dst) {
    int e = blockIdx.x * blockDim.x + threadIdx.x;
    if (e < NE) {
        int p = atomicAdd(&g_cur[dst[e]], 1);
        g_eidx[p] = e;
    }
}

// ---------------- pull-gather: agg[n] = sum_in-edges h[src] * w ----------------
__global__ void k_gather(const int* __restrict__ src, const float* __restrict__ w) {
    int idx = blockIdx.x * blockDim.x + threadIdx.x;   // NN*64
    int n = idx >> 6, q = idx & 63;
    int j0 = g_off[n], j1 = g_off[n + 1];
    float4 acc = make_float4(0.f, 0.f, 0.f, 0.f);
    for (int j = j0; j < j1; j++) {
        int e = g_eidx[j];
        int s = src[e];
        float ww = w[e];
        float4 v = ((const float4*)(g_h + (size_t)s * HD))[q];
        acc.x += v.x * ww; acc.y += v.y * ww;
        acc.z += v.z * ww; acc.w += v.w * ww;
    }
    ((float4*)(g_agg + (size_t)n * HD))[q] = acc;
}

// ---------------- last layer: per-graph sum of all node features ----------------
__global__ void k_rootsum() {
    int g = blockIdx.x;
    int c = blockIdx.y;
    int t = threadIdx.x;
    int r0 = c * 256;
    int r1 = r0 + 256; if (r1 > TREE_TOTAL) r1 = TREE_TOTAL;
    float s = 0.f;
    const float* base = g_h + ((size_t)g * TREE_TOTAL) * HD + t;
    for (int r = r0; r < r1; r++) s += base[(size_t)r * HD];
    atomicAdd(&g_root[g * HD + t], s);
}

// ---------------- BN -> per-column scale/shift; re-zero stats ----------------
__global__ void k_makescale(const float* __restrict__ gamma, const float* __restrict__ beta) {
    int t = threadIdx.x;
    double m = g_sum[t] / (double)NN;
    double v = g_sqsum[t] / (double)NN - m * m;
    if (v < 0.0) v = 0.0;
    double rs = 1.0 / sqrt(v + (double)BN_EPS);
    float sc = gamma[t] * (float)rs;
    g_scale[t] = sc;
    g_shift[t] = beta[t] - (float)m * sc;
    g_sum[t] = 0.0;
    g_sqsum[t] = 0.0;
}

// ============================================================================
// BF16x3 tensor-core GEMM, full-width tiles: C[128,256] per CTA, grid = 1024.
// (exact round-11 champion configuration)
// ============================================================================
#define GPA 136                     // A smem row stride (u32)
#define A_WORDS (8 * GPA)           // 1088 per matrix
#define BROW 12                     // B smem row stride (u32), 48B (16B aligned)
#define B_WORDS (256 * BROW)        // 3072 per matrix
#define STAGE_WORDS (2 * A_WORDS + 2 * B_WORDS)   // 8320
#define STATS_OFF (2 * STAGE_WORDS)               // 16640
#define SMEM_WORDS (STATS_OFF + 512)
#define SMEM_BYTES (SMEM_WORDS * 4)               // 68608

__device__ __forceinline__ void cp16(uint32_t saddr, const void* gptr) {
    asm volatile("cp.async.cg.shared.global [%0], [%1], 16;"
                 :: "r"(saddr), "l"(gptr) : "memory");
}

template <int MODE>
__global__ void __launch_bounds__(512, 1)
k_gemm_tc(const float* __restrict__ A1, const float* __restrict__ A2,
          const uint32_t* __restrict__ Wh, const uint32_t* __restrict__ Wl,
          const float* __restrict__ bias, float* __restrict__ C) {
    extern __shared__ uint32_t dyn[];
    float* s_sum = (float*)(dyn + STATS_OFF);
    float* s_ss  = (float*)(dyn + STATS_OFF + 256);
    const uint32_t smem_base = (uint32_t)__cvta_generic_to_shared(dyn);

    const int m0 = blockIdx.x * 128;
    const int tid = threadIdx.x;
    const int lane = tid & 31;
    const int warp = tid >> 5;
    const int wm = warp & 3;        // 32-row slab
    const int wn = warp >> 2;       // 64-col slab

    const int a_row = tid >> 2;     // 0..127
    const int a_kq  = tid & 3;      // float4 within 16-wide k
    const int b_row = tid >> 1;     // 0..255
    const int b_c   = tid & 1;      // half-row chunk

    const int grow = m0 + a_row;
    const bool rok = grow < NN;
    const float* rootrow = nullptr;
    if (MODE == 2 && rok && (grow % TREE_TOTAL) == 0)
        rootrow = g_root + (grow / TREE_TOTAL) * HD;

    if (tid < 256) { s_sum[tid] = 0.f; s_ss[tid] = 0.f; }

    float acc[2][8][4];
#pragma unroll
    for (int i = 0; i < 2; i++)
#pragma unroll
        for (int j = 0; j < 8; j++)
#pragma unroll
            for (int q = 0; q < 4; q++) acc[i][j][q] = 0.f;

    float4 va;

    auto ldgA = [&](int kt) {
        int kg = kt * 16 + a_kq * 4;
        if (rok) {
            va = *(const float4*)(A1 + (size_t)grow * HD + kg);
            if (MODE == 0) {
                float4 w4 = *(const float4*)(A2 + (size_t)grow * HD + kg);
                va.x += w4.x; va.y += w4.y; va.z += w4.z; va.w += w4.w;
            } else if (MODE == 1) {
                float4 sc = *(const float4*)(g_scale + kg);
                float4 sh = *(const float4*)(g_shift + kg);
                va.x = fmaxf(va.x * sc.x + sh.x, 0.f);
                va.y = fmaxf(va.y * sc.y + sh.y, 0.f);
                va.z = fmaxf(va.z * sc.z + sh.z, 0.f);
                va.w = fmaxf(va.w * sc.w + sh.w, 0.f);
            } else if (MODE == 2) {
                if (rootrow) {
                    va.x += rootrow[kg + 0]; va.y += rootrow[kg + 1];
                    va.z += rootrow[kg + 2]; va.w += rootrow[kg + 3];
                }
            }
        } else {
            va = make_float4(0.f, 0.f, 0.f, 0.f);
        }
    };
    auto cpB = [&](int kt, int stage) {
        int goff = b_row * 128 + kt * 8 + b_c * 4;
        uint32_t soff = (stage * STAGE_WORDS + 2 * A_WORDS
                         + b_row * BROW + b_c * 4) * 4;  // byte offset, BH region
        cp16(smem_base + soff, Wh + goff);
        cp16(smem_base + soff + B_WORDS * 4, Wl + goff); // BL region
    };
    auto stsA = [&](int stage) {
        uint32_t* AH = dyn + stage * STAGE_WORDS;
        uint32_t* AL = AH + A_WORDS;
        uint32_t h0, l0, h1, l1;
        int p0 = (a_kq * 2) * GPA + a_row;
        int p1 = (a_kq * 2 + 1) * GPA + a_row;
        split2(va.x, va.y, h0, l0);
        split2(va.z, va.w, h1, l1);
        AH[p0] = h0; AH[p1] = h1;
        AL[p0] = l0; AL[p1] = l1;
    };

    // prologue
    ldgA(0);
    cpB(0, 0);
    asm volatile("cp.async.commit_group;" ::: "memory");
    stsA(0);
    asm volatile("cp.async.wait_group 0;" ::: "memory");
    __syncthreads();

    const int kl = lane & 3;
    const int rbase = wm * 32 + (lane >> 2);
    const int nbase = wn * 64 + (lane >> 2);

#define MMA(ACC, Af, Bf)                                                      \
    asm volatile(                                                             \
        "mma.sync.aligned.m16n8k16.row.col.f32.bf16.bf16.f32 "                \
        "{%0,%1,%2,%3}, {%4,%5,%6,%7}, {%8,%9}, {%0,%1,%2,%3};"               \
        : "+f"((ACC)[0]), "+f"((ACC)[1]), "+f"((ACC)[2]), "+f"((ACC)[3])      \
        : "r"((Af)[0]), "r"((Af)[1]), "r"((Af)[2]), "r"((Af)[3]),             \
          "r"((Bf)[0]), "r"((Bf)[1]))

#pragma unroll 1
    for (int kt = 0; kt < 16; kt++) {
        const int cur = kt & 1;
        if (kt < 15) {
            ldgA(kt + 1);
            cpB(kt + 1, cur ^ 1);
            asm volatile("cp.async.commit_group;" ::: "memory");
        }

        const uint32_t* AH = dyn + cur * STAGE_WORDS;
        const uint32_t* AL = AH + A_WORDS;
        const uint32_t* BH = AL + A_WORDS;
        const uint32_t* BL = BH + B_WORDS;

        // phase 1: al . bh
        uint32_t fa[2][4], fb[8][2];
#pragma unroll
        for (int mt = 0; mt < 2; mt++) {
            int r = rbase + mt * 16;
            fa[mt][0] = AL[kl * GPA + r];
            fa[mt][1] = AL[kl * GPA + r + 8];
            fa[mt][2] = AL[(kl + 4) * GPA + r];
            fa[mt][3] = AL[(kl + 4) * GPA + r + 8];
        }
#pragma unroll
        for (int nt = 0; nt < 8; nt++) {
            int n = nbase + nt * 8;
            fb[nt][0] = BH[n * BROW + kl];
            fb[nt][1] = BH[n * BROW + kl + 4];
        }
#pragma unroll
        for (int mt = 0; mt < 2; mt++)
#pragma unroll
            for (int nt = 0; nt < 8; nt++)
                MMA(acc[mt][nt], fa[mt], fb[nt]);

        // phase 2: ah . bh
        uint32_t fa2[2][4];
#pragma unroll
        for (int mt = 0; mt < 2; mt++) {
            int r = rbase + mt * 16;
            fa2[mt][0] = AH[kl * GPA + r];
            fa2[mt][1] = AH[kl * GPA + r + 8];
            fa2[mt][2] = AH[(kl + 4) * GPA + r];
            fa2[mt][3] = AH[(kl + 4) * GPA + r + 8];
        }
#pragma unroll
        for (int mt = 0; mt < 2; mt++)
#pragma unroll
            for (int nt = 0; nt < 8; nt++)
                MMA(acc[mt][nt], fa2[mt], fb[nt]);

        // phase 3: ah . bl (overwrite fb)
#pragma unroll
        for (int nt = 0; nt < 8; nt++) {
            int n = nbase + nt * 8;
            fb[nt][0] = BL[n * BROW + kl];
            fb[nt][1] = BL[n * BROW + kl + 4];
        }
#pragma unroll
        for (int mt = 0; mt < 2; mt++)
#pragma unroll
            for (int nt = 0; nt < 8; nt++)
                MMA(acc[mt][nt], fa2[mt], fb[nt]);

        if (kt < 15) {
            stsA(cur ^ 1);
            asm volatile("cp.async.wait_group 0;" ::: "memory");
            __syncthreads();
        }
    }
#undef MMA

    // ---- epilogue: bias add, store, fused column stats ----
#pragma unroll
    for (int nt = 0; nt < 8; nt++) {
        int c = wn * 64 + nt * 8 + (lane & 3) * 2;
        float bv0 = bias[c], bv1 = bias[c + 1];
        float s0 = 0.f, s1 = 0.f, q0 = 0.f, q1 = 0.f;
#pragma unroll
        for (int mt = 0; mt < 2; mt++) {
            int r = m0 + wm * 32 + mt * 16 + (lane >> 2);
#pragma unroll
            for (int hh = 0; hh < 2; hh++) {
                int rr = r + hh * 8;
                if (rr < NN) {
                    float v0 = acc[mt][nt][hh * 2 + 0] + bv0;
                    float v1 = acc[mt][nt][hh * 2 + 1] + bv1;
                    *(float2*)(C + (size_t)rr * HD + c) = make_float2(v0, v1);
                    s0 += v0; s1 += v1;
                    q0 += v0 * v0; q1 += v1 * v1;
                }
            }
        }
#pragma unroll
        for (int o = 4; o < 32; o <<= 1) {
            s0 += __shfl_xor_sync(0xffffffffu, s0, o);
            s1 += __shfl_xor_sync(0xffffffffu, s1, o);
            q0 += __shfl_xor_sync(0xffffffffu, q0, o);
            q1 += __shfl_xor_sync(0xffffffffu, q1, o);
        }
        if ((lane >> 2) == 0) {
            atomicAdd(&s_sum[c],     s0);
            atomicAdd(&s_sum[c + 1], s1);
            atomicAdd(&s_ss[c],      q0);
            atomicAdd(&s_ss[c + 1],  q1);
        }
    }
    __syncthreads();
    if (tid < 256) {
        atomicAdd(&g_sum[tid],   (double)s_sum[tid]);
        atomicAdd(&g_sqsum[tid], (double)s_ss[tid]);
    }
}

// ---------------- residual + LayerNorm: h = LN(h + relu(y2*s+t)) ----------------
__global__ void k_resln(const float* __restrict__ y2,
                        const float* __restrict__ lng, const float* __restrict__ lnb) {
    const int w = threadIdx.x >> 5, l = threadIdx.x & 31;
    const int r = blockIdx.x * 8 + w;
    const float4* hrow = (const float4*)(g_h + (size_t)r * HD);
    const float4* yrow = (const float4*)(y2 + (size_t)r * HD);

    float4 u[2];
    float s = 0.f, ss = 0.f;
#pragma unroll
    for (int i = 0; i < 2; i++) {
        int c4 = l + i * 32;
        float4 hv = hrow[c4];
        float4 yv = yrow[c4];
        float4 sc = ((const float4*)g_scale)[c4];
        float4 sh = ((const float4*)g_shift)[c4];
        float4 uu;
        uu.x = hv.x + fmaxf(yv.x * sc.x + sh.x, 0.f);
        uu.y = hv.y + fmaxf(yv.y * sc.y + sh.y, 0.f);
        uu.z = hv.z + fmaxf(yv.z * sc.z + sh.z, 0.f);
        uu.w = hv.w + fmaxf(yv.w * sc.w + sh.w, 0.f);
        u[i] = uu;
        s  += uu.x + uu.y + uu.z + uu.w;
        ss += uu.x * uu.x + uu.y * uu.y + uu.z * uu.z + uu.w * uu.w;
    }
#pragma unroll
    for (int o = 16; o > 0; o >>= 1) {
        s  += __shfl_xor_sync(0xffffffffu, s, o);
        ss += __shfl_xor_sync(0xffffffffu, ss, o);
    }
    float mean = s * (1.f / HD);
    float var = ss * (1.f / HD) - mean * mean;
    if (var < 0.f) var = 0.f;
    float rs = rsqrtf(var + LN_EPS);

    float4* orow = (float4*)(g_h + (size_t)r * HD);
#pragma unroll
    for (int i = 0; i < 2; i++) {
        int c4 = l + i * 32;
        float4 gg = ((const float4*)lng)[c4];
        float4 bb = ((const float4*)lnb)[c4];
        float4 uu = u[i];
        float4 o4;
        o4.x = gg.x * (uu.x - mean) * rs + bb.x;
        o4.y = gg.y * (uu.y - mean) * rs + bb.y;
        o4.z = gg.z * (uu.z - mean) * rs + bb.z;
        o4.w = gg.w * (uu.w - mean) * rs + bb.w;
        orow[c4] = o4;
    }
}

// ---------------- readout: out[g,o] = h[root_g] . Wout[o] ----------------
__global__ void k_out(const float* __restrict__ Wout, float* __restrict__ out) {
    int g = blockIdx.x;
    int w = threadIdx.x >> 5;
    int l = threadIdx.x & 31;
    const float* hr = g_h + (size_t)g * TREE_TOTAL * HD;
    const float* wr = Wout + (size_t)w * HD;
    float s = 0.f;
#pragma unroll
    for (int k = l; k < HD; k += 32) s += hr[k] * wr[k];
#pragma unroll
    for (int o = 16; o > 0; o >>= 1) s += __shfl_down_sync(0xffffffffu, s, o);
    if (l == 0) out[g * 32 + w] = s;
}

// ---------------- launch ----------------
extern "C" void kernel_launch(void* const* d_in, const int* in_sizes, int n_in,
                              void* d_out, int out_size) {
    const int*   x    = (const int*)d_in[0];
    const int*   esrc = (const int*)d_in[1];
    const int*   edst = (const int*)d_in[2];
    const float* ew   = (const float*)d_in[3];
    const float* en   = (const float*)d_in[6];
    const float* el   = (const float*)d_in[7];
    const float* W1   = (const float*)d_in[8];
    const float* b1   = (const float*)d_in[9];
    const float* g1   = (const float*)d_in[10];
    const float* be1  = (const float*)d_in[11];
    const float* W2   = (const float*)d_in[12];
    const float* b2   = (const float*)d_in[13];
    const float* g2   = (const float*)d_in[14];
    const float* be2  = (const float*)d_in[15];
    const float* lng  = (const float*)d_in[16];
    const float* lnb  = (const float*)d_in[17];
    const float* Wout = (const float*)d_in[18];
    float* out = (float*)d_out;

    float *h, *agg, *y1, *y2, *root;
    uint32_t *Wh, *Wl;
    int* cnt;
    cudaGetSymbolAddress((void**)&h,    g_h);
    cudaGetSymbolAddress((void**)&agg,  g_agg);
    cudaGetSymbolAddress((void**)&y1,   g_y1);
    cudaGetSymbolAddress((void**)&y2,   g_y2);
    cudaGetSymbolAddress((void**)&root, g_root);
    cudaGetSymbolAddress((void**)&Wh,   g_Wh);
    cudaGetSymbolAddress((void**)&Wl,   g_Wl);
    cudaGetSymbolAddress((void**)&cnt,  g_cnt);

    cudaFuncSetAttribute(k_gemm_tc<0>, cudaFuncAttributeMaxDynamicSharedMemorySize, SMEM_BYTES);
    cudaFuncSetAttribute(k_gemm_tc<1>, cudaFuncAttributeMaxDynamicSharedMemorySize, SMEM_BYTES);
    cudaFuncSetAttribute(k_gemm_tc<2>, cudaFuncAttributeMaxDynamicSharedMemorySize, SMEM_BYTES);

    const int ggrid = (NN + 127) / 128;   // 1024
    const int sblocks = (NN + 255) / 256; // 512

    // per-launch CSR build (in-edges by destination)
    cudaMemsetAsync(cnt, 0, NN * sizeof(int));
    k_splitW<<<(8 * 256 * 128) / 256, 256>>>(W1, W2);
    k_embed<<<(NN * 64) / 256, 256>>>(x, en, el);
    k_count<<<(NE + 255) / 256, 256>>>(edst);
    k_scan1<<<sblocks, 256>>>();
    k_scan2<<<1, 512>>>();
    k_scan3<<<sblocks, 256>>>();
    k_fill<<<(NE + 255) / 256, 256>>>(edst);

    for (int i = 0; i < NL; i++) {
        const uint32_t* Wh1 = Wh + (size_t)i * 32768;
        const uint32_t* Wl1 = Wl + (size_t)i * 32768;
        const uint32_t* Wh2 = Wh + (size_t)(i + 4) * 32768;
        const uint32_t* Wl2 = Wl + (size_t)(i + 4) * 32768;
        const float* b1i = b1 + i * HD;
        const float* b2i = b2 + i * HD;
        const float* g1i = g1 + i * HD;
        const float* g2i = g2 + i * HD;
        const float* be1i = be1 + i * HD;
        const float* be2i = be2 + i * HD;
        const float* lngi = lng + i * HD;
        const float* lnbi = lnb + i * HD;

        if (i < NL - 1) {
            k_gather<<<(NN * 64) / 256, 256>>>(esrc, ew);
            k_gemm_tc<0><<<ggrid, 512, SMEM_BYTES>>>(h, agg, Wh1, Wl1, b1i, y1);
        } else {
            cudaMemsetAsync(root, 0, (size_t)NG * HD * sizeof(float));
            k_rootsum<<<dim3(NG, 8), 256>>>();
            k_gemm_tc<2><<<ggrid, 512, SMEM_BYTES>>>(h, nullptr, Wh1, Wl1, b1i, y1);
        }
        k_makescale<<<1, 256>>>(g1i, be1i);
        k_gemm_tc<1><<<ggrid, 512, SMEM_BYTES>>>(y1, nullptr, Wh2, Wl2, b2i, y2);
        k_makescale<<<1, 256>>>(g2i, be2i);
        k_resln<<<NN / 8, 256>>>(y2, lngi, lnbi);
    }

    k_out<<<NG, 1024>>>(Wout, out);
}